// round 4
// baseline (speedup 1.0000x reference)
#include <cuda_runtime.h>
#include <cuda_bf16.h>

#define NTOKEN 150000
#define NINP   64
#define NEDGE  2400000
#define NBL    12800
#define BMWORDS ((NTOKEN + 31) / 32)

// ---------------------------------------------------------------------------
// Scratch
// ---------------------------------------------------------------------------
__device__ __align__(16) float g_y[NTOKEN * NINP];   // P X (valid at needed rows)
__device__ __align__(16) float g_z[NTOKEN * NINP];   // P(PX) (valid at token rows)
__device__ int      g_deg[NTOKEN];
__device__ float    g_dinv[NTOKEN];
__device__ float    g_c[NTOKEN];                     // valid at token rows
__device__ unsigned g_tokbm[BMWORDS];
__device__ unsigned g_bmneed[BMWORDS];
__device__ int2     g_ce[NEDGE];                     // stashed (s,d)
__device__ int      g_off[NTOKEN + 1];               // CSR offsets (by dst)
__device__ int      g_cur[NTOKEN];                   // fill cursors
__device__ int      g_csr[NEDGE];                    // src per slot
__device__ int      g_toklist[NBL];                  // unique token nodes
__device__ int      g_ntok;
__device__ float    g_W12[NINP * NINP];
__device__ float    g_bW[NINP];
__device__ int      g_is64;

// ---------------------------------------------------------------------------
__device__ __forceinline__ long long ld_idx(const void* p, long long i, int is64) {
    return is64 ? ((const long long*)p)[i] : (long long)((const int*)p)[i];
}

// K0: int64 vs int32 storage detection
__global__ void k_detect(const void* __restrict__ eidx) {
    const long long* p = (const long long*)eidx;
    int ok = 1;
    #pragma unroll
    for (int i = 0; i < 16; i++) {
        long long v = p[i];
        if (v < 0 || v >= NTOKEN) ok = 0;
    }
    g_is64 = ok;
}

// K1: zero small state
__global__ void k_zero() {
    int i = blockIdx.x * blockDim.x + threadIdx.x;
    if (i < NTOKEN) g_deg[i] = 0;
    if (i < BMWORDS) { g_tokbm[i] = 0u; g_bmneed[i] = 0u; }
    if (i == 0) g_ntok = 0;
}

// K2: token bitmap + unique-token list + bmneed(token)
__global__ void k_tokbm(const void* __restrict__ inp) {
    int i = blockIdx.x * blockDim.x + threadIdx.x;
    if (i >= NBL) return;
    int t = (int)ld_idx(inp, i, g_is64);
    unsigned bit = 1u << (t & 31);
    unsigned old = atomicOr(&g_tokbm[t >> 5], bit);
    if (!(old & bit)) g_toklist[atomicAdd(&g_ntok, 1)] = t;
    atomicOr(&g_bmneed[t >> 5], bit);
}

// K3: decode+stash edges, degree count, bmneed(src of token-dst edges)
__global__ void k_deg(const void* __restrict__ eidx) {
    int e = blockIdx.x * blockDim.x + threadIdx.x;
    if (e >= NEDGE) return;
    int is64 = g_is64;
    int s = (int)ld_idx(eidx, e, is64);
    int d = (int)ld_idx(eidx, (long long)NEDGE + e, is64);
    g_ce[e] = make_int2(s, d);
    atomicAdd(&g_deg[d], 1);
    if ((g_tokbm[d >> 5] >> (d & 31)) & 1u)
        atomicOr(&g_bmneed[s >> 5], 1u << (s & 31));
}

// K4: exclusive prefix scan of degrees -> g_off, g_cur.  <<<1,1024>>>
__global__ void k_scan() {
    __shared__ int sums[1024];
    const int CH = (NTOKEN + 1023) / 1024;          // 147
    int t = threadIdx.x;
    int b = t * CH;
    int e = min(b + CH, NTOKEN);
    int s = 0;
    for (int i = b; i < e; i++) s += g_deg[i];
    sums[t] = s;
    __syncthreads();
    for (int off = 1; off < 1024; off <<= 1) {
        int u = (t >= off) ? sums[t - off] : 0;
        __syncthreads();
        sums[t] += u;
        __syncthreads();
    }
    int run = sums[t] - s;                           // exclusive chunk base
    for (int i = b; i < e; i++) {
        g_off[i] = run; g_cur[i] = run;
        run += g_deg[i];
    }
    if (t == (NTOKEN - 1) / CH) g_off[NTOKEN] = run;
}

// K5: fill CSR, only for dst in bmneed
__global__ void k_fill() {
    int e = blockIdx.x * blockDim.x + threadIdx.x;
    if (e >= NEDGE) return;
    int2 sd = g_ce[e];
    if (!((g_bmneed[sd.y >> 5] >> (sd.y & 31)) & 1u)) return;
    int pos = atomicAdd(&g_cur[sd.y], 1);
    g_csr[pos] = sd.x;
}

// K6: dinv
__global__ void k_dinv() {
    int i = blockIdx.x * blockDim.x + threadIdx.x;
    if (i < NTOKEN) g_dinv[i] = rsqrtf((float)g_deg[i] + 1.0f);
}

// K7: gather pass 1 — warp per node d in bmneed:
//     y[d] = sum_in w * X[s] + dinv_d^2 * X[d]
__global__ void k_gather1(const float* __restrict__ X) {
    int w = (int)(((long long)blockIdx.x * blockDim.x + threadIdx.x) >> 5);
    if (w >= NTOKEN) return;
    int d = w;
    if (!((g_bmneed[d >> 5] >> (d & 31)) & 1u)) return;
    int lane = threadIdx.x & 31;
    int beg = g_off[d], end = g_cur[d];              // cur = beg + inserted count
    float dd = g_dinv[d];
    float ax = 0.f, ay = 0.f;
    int i = beg;
    for (; i + 4 <= end; i += 4) {
        int s0 = __ldg(&g_csr[i]),     s1 = __ldg(&g_csr[i + 1]);
        int s2 = __ldg(&g_csr[i + 2]), s3 = __ldg(&g_csr[i + 3]);
        float w0 = __ldg(&g_dinv[s0]) * dd, w1 = __ldg(&g_dinv[s1]) * dd;
        float w2 = __ldg(&g_dinv[s2]) * dd, w3 = __ldg(&g_dinv[s3]) * dd;
        float2 x0 = __ldg(((const float2*)(X + s0 * NINP)) + lane);
        float2 x1 = __ldg(((const float2*)(X + s1 * NINP)) + lane);
        float2 x2 = __ldg(((const float2*)(X + s2 * NINP)) + lane);
        float2 x3 = __ldg(((const float2*)(X + s3 * NINP)) + lane);
        ax += w0 * x0.x + w1 * x1.x + w2 * x2.x + w3 * x3.x;
        ay += w0 * x0.y + w1 * x1.y + w2 * x2.y + w3 * x3.y;
    }
    for (; i < end; i++) {
        int s = __ldg(&g_csr[i]);
        float ww = __ldg(&g_dinv[s]) * dd;
        float2 x = __ldg(((const float2*)(X + s * NINP)) + lane);
        ax += ww * x.x; ay += ww * x.y;
    }
    float2 xs = __ldg(((const float2*)(X + d * NINP)) + lane);
    float sw = dd * dd;
    ax += sw * xs.x; ay += sw * xs.y;
    ((float2*)(g_y + d * NINP))[lane] = make_float2(ax, ay);
}

// K8: gather pass 2 — warp per unique token node t:
//     z[t] = sum_in w * y[s] + dinv_t^2 * y[t];  c[t] = sum_in w + dinv_t^2
__global__ void k_gather2() {
    int w = (int)(((long long)blockIdx.x * blockDim.x + threadIdx.x) >> 5);
    if (w >= g_ntok) return;
    int d = g_toklist[w];
    int lane = threadIdx.x & 31;
    int beg = g_off[d], end = g_cur[d];
    float dd = g_dinv[d];
    float ax = 0.f, ay = 0.f, cw = 0.f;
    int i = beg;
    for (; i + 4 <= end; i += 4) {
        int s0 = __ldg(&g_csr[i]),     s1 = __ldg(&g_csr[i + 1]);
        int s2 = __ldg(&g_csr[i + 2]), s3 = __ldg(&g_csr[i + 3]);
        float w0 = __ldg(&g_dinv[s0]) * dd, w1 = __ldg(&g_dinv[s1]) * dd;
        float w2 = __ldg(&g_dinv[s2]) * dd, w3 = __ldg(&g_dinv[s3]) * dd;
        float2 x0 = ((const float2*)(g_y + s0 * NINP))[lane];
        float2 x1 = ((const float2*)(g_y + s1 * NINP))[lane];
        float2 x2 = ((const float2*)(g_y + s2 * NINP))[lane];
        float2 x3 = ((const float2*)(g_y + s3 * NINP))[lane];
        ax += w0 * x0.x + w1 * x1.x + w2 * x2.x + w3 * x3.x;
        ay += w0 * x0.y + w1 * x1.y + w2 * x2.y + w3 * x3.y;
        cw += w0 + w1 + w2 + w3;
    }
    for (; i < end; i++) {
        int s = __ldg(&g_csr[i]);
        float ww = __ldg(&g_dinv[s]) * dd;
        float2 x = ((const float2*)(g_y + s * NINP))[lane];
        ax += ww * x.x; ay += ww * x.y; cw += ww;
    }
    float sw = dd * dd;
    float2 ys = ((const float2*)(g_y + d * NINP))[lane];
    ax += sw * ys.x; ay += sw * ys.y; cw += sw;
    ((float2*)(g_z + d * NINP))[lane] = make_float2(ax, ay);
    if (lane == 0) g_c[d] = cw;
}

// K9: W12 = W1@W2, bW = b1@W2
__global__ void k_w12(const float* __restrict__ W1, const float* __restrict__ b1,
                      const float* __restrict__ W2) {
    int j = threadIdx.x;
    int b = blockIdx.x;
    float acc = 0.f;
    if (b < NINP) {
        #pragma unroll 8
        for (int k = 0; k < 2 * NINP; k++) acc += W1[b * 2 * NINP + k] * W2[k * NINP + j];
        g_W12[b * NINP + j] = acc;
    } else {
        #pragma unroll 8
        for (int k = 0; k < 2 * NINP; k++) acc += b1[k] * W2[k * NINP + j];
        g_bW[j] = acc;
    }
}

// K10: out[n,j] = z[tok].W12[:,j] + c[tok]*bW[j] + b2[j]
__global__ void k_out(const void* __restrict__ inp, const float* __restrict__ b2,
                      float* __restrict__ out) {
    __shared__ float sW[NINP * NINP];
    __shared__ float sz[4][NINP];
    __shared__ float sc[4];
    int tid = threadIdx.x;
    int g = tid >> 6;
    int j = tid & 63;
    int n = blockIdx.x * 4 + g;
    int is64 = g_is64;

    for (int i = tid; i < NINP * NINP; i += 256) sW[i] = g_W12[i];
    int tok = (int)ld_idx(inp, n, is64);
    sz[g][j] = g_z[tok * NINP + j];
    if (j == 0) sc[g] = g_c[tok];
    __syncthreads();

    float acc = 0.f;
    #pragma unroll
    for (int i = 0; i < NINP; i++) acc += sz[g][i] * sW[i * NINP + j];
    out[n * NINP + j] = acc + sc[g] * g_bW[j] + b2[j];
}

// ---------------------------------------------------------------------------
extern "C" void kernel_launch(void* const* d_in, const int* in_sizes, int n_in,
                              void* d_out, int out_size) {
    const float* emb = (const float*)d_in[0];
    const float* W1  = (const float*)d_in[1];
    const float* b1  = (const float*)d_in[2];
    const float* W2  = (const float*)d_in[3];
    const float* b2  = (const float*)d_in[4];
    const void*  inp = d_in[5];
    const void*  eidx = d_in[7];
    float* out = (float*)d_out;

    const int TB = 256;
    k_detect<<<1, 1>>>(eidx);
    k_zero<<<(NTOKEN + TB - 1) / TB, TB>>>();
    k_tokbm<<<(NBL + TB - 1) / TB, TB>>>(inp);
    k_deg<<<(NEDGE + TB - 1) / TB, TB>>>(eidx);
    k_scan<<<1, 1024>>>();
    k_fill<<<(NEDGE + TB - 1) / TB, TB>>>();
    k_dinv<<<(NTOKEN + TB - 1) / TB, TB>>>();
    k_gather1<<<(NTOKEN * 32 + TB - 1) / TB, TB>>>(emb);
    k_gather2<<<(NBL * 32 + TB - 1) / TB, TB>>>();
    k_w12<<<NINP + 1, NINP>>>(W1, b1, W2);
    k_out<<<NBL / 4, TB>>>(inp, b2, out);
}

// round 5
// speedup vs baseline: 2.4367x; 2.4367x over previous
#include <cuda_runtime.h>
#include <cuda_bf16.h>

#define NTOKEN 150000
#define NINP   64
#define NEDGE  2400000
#define NBL    12800
#define BMWORDS ((NTOKEN + 31) / 32)
#define NB_SCAN ((NTOKEN + 255) / 256)   // 586 scan blocks

// ---------------------------------------------------------------------------
// Scratch
// ---------------------------------------------------------------------------
__device__ __align__(16) float g_y[NTOKEN * NINP];   // P X (valid at needed rows)
__device__ __align__(16) float g_z[NTOKEN * NINP];   // P(PX) (valid at token rows)
__device__ int      g_deg[NTOKEN];
__device__ float    g_dinv[NTOKEN];
__device__ float    g_c[NTOKEN];                     // valid at token rows
__device__ unsigned g_tokbm[BMWORDS];
__device__ unsigned g_bmneed[BMWORDS];
__device__ int2     g_ce[NEDGE];                     // stashed (s,d)
__device__ int      g_off[NTOKEN];                   // CSR offsets (by dst)
__device__ int      g_cur[NTOKEN];                   // fill cursors
__device__ int      g_csr[NEDGE];                    // src per slot
__device__ int      g_bsum[NB_SCAN];                 // per-block degree sums
__device__ int      g_bbase[NB_SCAN];                // per-block exclusive bases
__device__ int      g_toklist[NBL];                  // unique token nodes
__device__ int      g_ntok;
__device__ int      g_needlist[NTOKEN];              // nodes needing y
__device__ int      g_nneed;
__device__ float    g_W12[NINP * NINP];
__device__ float    g_bW[NINP];
__device__ int      g_is64;

// ---------------------------------------------------------------------------
__device__ __forceinline__ long long ld_idx(const void* p, long long i, int is64) {
    return is64 ? ((const long long*)p)[i] : (long long)((const int*)p)[i];
}

// K0: int64 vs int32 storage detection
__global__ void k_detect(const void* __restrict__ eidx) {
    const long long* p = (const long long*)eidx;
    int ok = 1;
    #pragma unroll
    for (int i = 0; i < 16; i++) {
        long long v = p[i];
        if (v < 0 || v >= NTOKEN) ok = 0;
    }
    g_is64 = ok;
}

// K1: zero small state
__global__ void k_zero() {
    int i = blockIdx.x * blockDim.x + threadIdx.x;
    if (i < NTOKEN) g_deg[i] = 0;
    if (i < BMWORDS) { g_tokbm[i] = 0u; g_bmneed[i] = 0u; }
    if (i == 0) { g_ntok = 0; g_nneed = 0; }
}

// K2: token bitmap + unique-token list + bmneed(token)
__global__ void k_tokbm(const void* __restrict__ inp) {
    int i = blockIdx.x * blockDim.x + threadIdx.x;
    if (i >= NBL) return;
    int t = (int)ld_idx(inp, i, g_is64);
    unsigned bit = 1u << (t & 31);
    unsigned old = atomicOr(&g_tokbm[t >> 5], bit);
    if (!(old & bit)) g_toklist[atomicAdd(&g_ntok, 1)] = t;
    atomicOr(&g_bmneed[t >> 5], bit);
}

// K3: decode+stash edges, degree count, bmneed(src of token-dst edges)
__global__ void k_deg(const void* __restrict__ eidx) {
    int e = blockIdx.x * blockDim.x + threadIdx.x;
    if (e >= NEDGE) return;
    int is64 = g_is64;
    int s = (int)ld_idx(eidx, e, is64);
    int d = (int)ld_idx(eidx, (long long)NEDGE + e, is64);
    g_ce[e] = make_int2(s, d);
    atomicAdd(&g_deg[d], 1);
    if ((g_tokbm[d >> 5] >> (d & 31)) & 1u)
        atomicOr(&g_bmneed[s >> 5], 1u << (s & 31));
}

// K4a: per-block degree sums (586 blocks x 256)
__global__ void k_bsum() {
    __shared__ int sm[256];
    int i = blockIdx.x * 256 + threadIdx.x;
    int v = (i < NTOKEN) ? g_deg[i] : 0;
    sm[threadIdx.x] = v;
    __syncthreads();
    for (int off = 128; off > 0; off >>= 1) {
        if (threadIdx.x < off) sm[threadIdx.x] += sm[threadIdx.x + off];
        __syncthreads();
    }
    if (threadIdx.x == 0) g_bsum[blockIdx.x] = sm[0];
}

// K4b: exclusive scan of 586 block sums. <<<1,1024>>>
__global__ void k_btop() {
    __shared__ int sm[1024];
    int t = threadIdx.x;
    int v = (t < NB_SCAN) ? g_bsum[t] : 0;
    sm[t] = v;
    __syncthreads();
    for (int off = 1; off < 1024; off <<= 1) {
        int u = (t >= off) ? sm[t - off] : 0;
        __syncthreads();
        sm[t] += u;
        __syncthreads();
    }
    if (t < NB_SCAN) g_bbase[t] = sm[t] - v;         // exclusive
}

// K4c: per-block exclusive scan + base -> g_off/g_cur; fused dinv
__global__ void k_offs() {
    __shared__ int sm[256];
    int t = threadIdx.x;
    int i = blockIdx.x * 256 + t;
    int d = (i < NTOKEN) ? g_deg[i] : 0;
    sm[t] = d;
    __syncthreads();
    for (int off = 1; off < 256; off <<= 1) {
        int u = (t >= off) ? sm[t - off] : 0;
        __syncthreads();
        sm[t] += u;
        __syncthreads();
    }
    if (i < NTOKEN) {
        int o = g_bbase[blockIdx.x] + sm[t] - d;     // exclusive
        g_off[i] = o;
        g_cur[i] = o;
        g_dinv[i] = rsqrtf((float)d + 1.0f);
    }
}

// K4d: compact bmneed -> dense need list
__global__ void k_needlist() {
    int i = blockIdx.x * blockDim.x + threadIdx.x;
    if (i >= BMWORDS) return;
    unsigned w = g_bmneed[i];
    if (!w) return;
    int base = atomicAdd(&g_nneed, __popc(w));
    while (w) {
        int b = __ffs(w) - 1;
        g_needlist[base++] = i * 32 + b;
        w &= w - 1u;
    }
}

// K5: fill CSR, only for dst in bmneed
__global__ void k_fill() {
    int e = blockIdx.x * blockDim.x + threadIdx.x;
    if (e >= NEDGE) return;
    int2 sd = g_ce[e];
    if (!((g_bmneed[sd.y >> 5] >> (sd.y & 31)) & 1u)) return;
    int pos = atomicAdd(&g_cur[sd.y], 1);
    g_csr[pos] = sd.x;
}

// K7: gather pass 1 — warp per needed node d:
//     y[d] = sum_in w * X[s] + dinv_d^2 * X[d]
__global__ void k_gather1(const float* __restrict__ X) {
    int w = (int)(((long long)blockIdx.x * blockDim.x + threadIdx.x) >> 5);
    if (w >= g_nneed) return;
    int d = g_needlist[w];
    int lane = threadIdx.x & 31;
    int beg = g_off[d], end = g_cur[d];              // cur = beg + inserted count
    float dd = g_dinv[d];
    float ax = 0.f, ay = 0.f;
    int i = beg;
    for (; i + 4 <= end; i += 4) {
        int s0 = __ldg(&g_csr[i]),     s1 = __ldg(&g_csr[i + 1]);
        int s2 = __ldg(&g_csr[i + 2]), s3 = __ldg(&g_csr[i + 3]);
        float w0 = __ldg(&g_dinv[s0]) * dd, w1 = __ldg(&g_dinv[s1]) * dd;
        float w2 = __ldg(&g_dinv[s2]) * dd, w3 = __ldg(&g_dinv[s3]) * dd;
        float2 x0 = __ldg(((const float2*)(X + s0 * NINP)) + lane);
        float2 x1 = __ldg(((const float2*)(X + s1 * NINP)) + lane);
        float2 x2 = __ldg(((const float2*)(X + s2 * NINP)) + lane);
        float2 x3 = __ldg(((const float2*)(X + s3 * NINP)) + lane);
        ax += w0 * x0.x + w1 * x1.x + w2 * x2.x + w3 * x3.x;
        ay += w0 * x0.y + w1 * x1.y + w2 * x2.y + w3 * x3.y;
    }
    for (; i < end; i++) {
        int s = __ldg(&g_csr[i]);
        float ww = __ldg(&g_dinv[s]) * dd;
        float2 x = __ldg(((const float2*)(X + s * NINP)) + lane);
        ax += ww * x.x; ay += ww * x.y;
    }
    float2 xs = __ldg(((const float2*)(X + d * NINP)) + lane);
    float sw = dd * dd;
    ax += sw * xs.x; ay += sw * xs.y;
    ((float2*)(g_y + d * NINP))[lane] = make_float2(ax, ay);
}

// K8: gather pass 2 — warp per unique token node t:
//     z[t] = sum_in w * y[s] + dinv_t^2 * y[t];  c[t] = sum_in w + dinv_t^2
__global__ void k_gather2() {
    int w = (int)(((long long)blockIdx.x * blockDim.x + threadIdx.x) >> 5);
    if (w >= g_ntok) return;
    int d = g_toklist[w];
    int lane = threadIdx.x & 31;
    int beg = g_off[d], end = g_cur[d];
    float dd = g_dinv[d];
    float ax = 0.f, ay = 0.f, cw = 0.f;
    int i = beg;
    for (; i + 4 <= end; i += 4) {
        int s0 = __ldg(&g_csr[i]),     s1 = __ldg(&g_csr[i + 1]);
        int s2 = __ldg(&g_csr[i + 2]), s3 = __ldg(&g_csr[i + 3]);
        float w0 = __ldg(&g_dinv[s0]) * dd, w1 = __ldg(&g_dinv[s1]) * dd;
        float w2 = __ldg(&g_dinv[s2]) * dd, w3 = __ldg(&g_dinv[s3]) * dd;
        float2 x0 = ((const float2*)(g_y + s0 * NINP))[lane];
        float2 x1 = ((const float2*)(g_y + s1 * NINP))[lane];
        float2 x2 = ((const float2*)(g_y + s2 * NINP))[lane];
        float2 x3 = ((const float2*)(g_y + s3 * NINP))[lane];
        ax += w0 * x0.x + w1 * x1.x + w2 * x2.x + w3 * x3.x;
        ay += w0 * x0.y + w1 * x1.y + w2 * x2.y + w3 * x3.y;
        cw += w0 + w1 + w2 + w3;
    }
    for (; i < end; i++) {
        int s = __ldg(&g_csr[i]);
        float ww = __ldg(&g_dinv[s]) * dd;
        float2 x = ((const float2*)(g_y + s * NINP))[lane];
        ax += ww * x.x; ay += ww * x.y; cw += ww;
    }
    float sw = dd * dd;
    float2 ys = ((const float2*)(g_y + d * NINP))[lane];
    ax += sw * ys.x; ay += sw * ys.y; cw += sw;
    ((float2*)(g_z + d * NINP))[lane] = make_float2(ax, ay);
    if (lane == 0) g_c[d] = cw;
}

// K9: W12 = W1@W2, bW = b1@W2
__global__ void k_w12(const float* __restrict__ W1, const float* __restrict__ b1,
                      const float* __restrict__ W2) {
    int j = threadIdx.x;
    int b = blockIdx.x;
    float acc = 0.f;
    if (b < NINP) {
        #pragma unroll 8
        for (int k = 0; k < 2 * NINP; k++) acc += W1[b * 2 * NINP + k] * W2[k * NINP + j];
        g_W12[b * NINP + j] = acc;
    } else {
        #pragma unroll 8
        for (int k = 0; k < 2 * NINP; k++) acc += b1[k] * W2[k * NINP + j];
        g_bW[j] = acc;
    }
}

// K10: out[n,j] = z[tok].W12[:,j] + c[tok]*bW[j] + b2[j]
__global__ void k_out(const void* __restrict__ inp, const float* __restrict__ b2,
                      float* __restrict__ out) {
    __shared__ float sW[NINP * NINP];
    __shared__ float sz[4][NINP];
    __shared__ float sc[4];
    int tid = threadIdx.x;
    int g = tid >> 6;
    int j = tid & 63;
    int n = blockIdx.x * 4 + g;
    int is64 = g_is64;

    for (int i = tid; i < NINP * NINP; i += 256) sW[i] = g_W12[i];
    int tok = (int)ld_idx(inp, n, is64);
    sz[g][j] = g_z[tok * NINP + j];
    if (j == 0) sc[g] = g_c[tok];
    __syncthreads();

    float acc = 0.f;
    #pragma unroll
    for (int i = 0; i < NINP; i++) acc += sz[g][i] * sW[i * NINP + j];
    out[n * NINP + j] = acc + sc[g] * g_bW[j] + b2[j];
}

// ---------------------------------------------------------------------------
extern "C" void kernel_launch(void* const* d_in, const int* in_sizes, int n_in,
                              void* d_out, int out_size) {
    const float* emb = (const float*)d_in[0];
    const float* W1  = (const float*)d_in[1];
    const float* b1  = (const float*)d_in[2];
    const float* W2  = (const float*)d_in[3];
    const float* b2  = (const float*)d_in[4];
    const void*  inp = d_in[5];
    const void*  eidx = d_in[7];
    float* out = (float*)d_out;

    const int TB = 256;
    k_detect<<<1, 1>>>(eidx);
    k_zero<<<(NTOKEN + TB - 1) / TB, TB>>>();
    k_tokbm<<<(NBL + TB - 1) / TB, TB>>>(inp);
    k_deg<<<(NEDGE + TB - 1) / TB, TB>>>(eidx);
    k_bsum<<<NB_SCAN, 256>>>();
    k_btop<<<1, 1024>>>();
    k_offs<<<NB_SCAN, 256>>>();
    k_needlist<<<(BMWORDS + TB - 1) / TB, TB>>>();
    k_fill<<<(NEDGE + TB - 1) / TB, TB>>>();
    k_gather1<<<(NTOKEN * 32 + TB - 1) / TB, TB>>>(emb);
    k_gather2<<<(NBL * 32 + TB - 1) / TB, TB>>>();
    k_w12<<<NINP + 1, NINP>>>(W1, b1, W2);
    k_out<<<NBL / 4, TB>>>(inp, b2, out);
}

// round 6
// speedup vs baseline: 2.5085x; 1.0295x over previous
#include <cuda_runtime.h>
#include <cuda_bf16.h>

#define NTOKEN 150000
#define NINP   64
#define NEDGE  2400000
#define NBL    12800
#define BMWORDS ((NTOKEN + 31) / 32)
#define NB_SCAN ((NTOKEN + 255) / 256)   // 586 scan blocks; 586*8 == BMWORDS

// ---------------------------------------------------------------------------
// Scratch
// ---------------------------------------------------------------------------
__device__ __align__(16) float g_y[NTOKEN * NINP];
__device__ __align__(16) float g_z[NTOKEN * NINP];
__device__ int      g_deg[NTOKEN];
__device__ float    g_dinv[NTOKEN];
__device__ float    g_c[NTOKEN];
__device__ unsigned g_tokbm[BMWORDS];
__device__ unsigned g_bmneed[BMWORDS];
__device__ __align__(16) int2 g_ce[NEDGE];           // stashed (s,d)
__device__ int      g_off[NTOKEN];
__device__ int      g_cur[NTOKEN];
__device__ int      g_csr[NEDGE];
__device__ int      g_bsum[NB_SCAN];
__device__ int      g_bbase[NB_SCAN];
__device__ int      g_toklist[NBL];
__device__ int      g_ntok;
__device__ int      g_needlist[NTOKEN];
__device__ int      g_nneed;
__device__ float    g_W12[NINP * NINP];
__device__ float    g_bW[NINP];
__device__ int      g_is64;

// ---------------------------------------------------------------------------
__device__ __forceinline__ long long ld_idx(const void* p, long long i, int is64) {
    return is64 ? ((const long long*)p)[i] : (long long)((const int*)p)[i];
}

// K1: zero small state + int64/int32 detection (thread 0)
__global__ void k_zero(const void* __restrict__ eidx) {
    int i = blockIdx.x * blockDim.x + threadIdx.x;
    if (i < NTOKEN) g_deg[i] = 0;
    if (i < BMWORDS) { g_tokbm[i] = 0u; g_bmneed[i] = 0u; }
    if (i == 0) {
        g_ntok = 0; g_nneed = 0;
        const long long* p = (const long long*)eidx;
        int ok = 1;
        #pragma unroll
        for (int k = 0; k < 16; k++) {
            long long v = p[k];
            if (v < 0 || v >= NTOKEN) ok = 0;
        }
        g_is64 = ok;
    }
}

// K2: token bitmap + unique-token list + bmneed(token)
__global__ void k_tokbm(const void* __restrict__ inp) {
    int i = blockIdx.x * blockDim.x + threadIdx.x;
    if (i >= NBL) return;
    int t = (int)ld_idx(inp, i, g_is64);
    unsigned bit = 1u << (t & 31);
    unsigned old = atomicOr(&g_tokbm[t >> 5], bit);
    if (!(old & bit)) g_toklist[atomicAdd(&g_ntok, 1)] = t;
    atomicOr(&g_bmneed[t >> 5], bit);
}

// K3: decode+stash edges, degree count, bmneed(src of token-dst edges)
__global__ void k_deg(const void* __restrict__ eidx) {
    int e = blockIdx.x * blockDim.x + threadIdx.x;
    if (e >= NEDGE) return;
    int is64 = g_is64;
    int s = (int)ld_idx(eidx, e, is64);
    int d = (int)ld_idx(eidx, (long long)NEDGE + e, is64);
    g_ce[e] = make_int2(s, d);
    atomicAdd(&g_deg[d], 1);
    if ((g_tokbm[d >> 5] >> (d & 31)) & 1u)
        atomicOr(&g_bmneed[s >> 5], 1u << (s & 31));
}

// K4a: per-block degree sums
__global__ void k_bsum() {
    __shared__ int sm[256];
    int i = blockIdx.x * 256 + threadIdx.x;
    int v = (i < NTOKEN) ? g_deg[i] : 0;
    sm[threadIdx.x] = v;
    __syncthreads();
    for (int off = 128; off > 0; off >>= 1) {
        if (threadIdx.x < off) sm[threadIdx.x] += sm[threadIdx.x + off];
        __syncthreads();
    }
    if (threadIdx.x == 0) g_bsum[blockIdx.x] = sm[0];
}

// K4b: exclusive scan of block sums. <<<1,1024>>>
__global__ void k_btop() {
    __shared__ int sm[1024];
    int t = threadIdx.x;
    int v = (t < NB_SCAN) ? g_bsum[t] : 0;
    sm[t] = v;
    __syncthreads();
    for (int off = 1; off < 1024; off <<= 1) {
        int u = (t >= off) ? sm[t - off] : 0;
        __syncthreads();
        sm[t] += u;
        __syncthreads();
    }
    if (t < NB_SCAN) g_bbase[t] = sm[t] - v;
}

// K4c: per-block scan + base -> off/cur; fused dinv; fused needlist compaction
__global__ void k_offs() {
    __shared__ int sm[256];
    int t = threadIdx.x;
    int i = blockIdx.x * 256 + t;
    int d = (i < NTOKEN) ? g_deg[i] : 0;
    sm[t] = d;
    __syncthreads();
    for (int off = 1; off < 256; off <<= 1) {
        int u = (t >= off) ? sm[t - off] : 0;
        __syncthreads();
        sm[t] += u;
        __syncthreads();
    }
    if (i < NTOKEN) {
        int o = g_bbase[blockIdx.x] + sm[t] - d;
        g_off[i] = o;
        g_cur[i] = o;
        g_dinv[i] = rsqrtf((float)d + 1.0f);
    }
    // needlist: this block owns bitmap words [blockIdx*8, blockIdx*8+8)
    if (t < 8) {
        int wi = blockIdx.x * 8 + t;
        if (wi < BMWORDS) {
            unsigned w = g_bmneed[wi];
            if (w) {
                int base = atomicAdd(&g_nneed, __popc(w));
                while (w) {
                    int b = __ffs(w) - 1;
                    g_needlist[base++] = wi * 32 + b;
                    w &= w - 1u;
                }
            }
        }
    }
}

// K5: fill CSR, only for dst in bmneed; 2 edges/thread via int4
__global__ void k_fill() {
    int t = blockIdx.x * blockDim.x + threadIdx.x;
    int e = t * 2;
    if (e >= NEDGE) return;
    int4 p = *(const int4*)&g_ce[e];                 // (s0,d0,s1,d1)
    if ((g_bmneed[p.y >> 5] >> (p.y & 31)) & 1u) {
        int pos = atomicAdd(&g_cur[p.y], 1);
        g_csr[pos] = p.x;
    }
    if ((g_bmneed[p.w >> 5] >> (p.w & 31)) & 1u) {
        int pos = atomicAdd(&g_cur[p.w], 1);
        g_csr[pos] = p.z;
    }
}

// K7: gather pass 1 — warp per needed node
__global__ void k_gather1(const float* __restrict__ X) {
    int w = (int)(((long long)blockIdx.x * blockDim.x + threadIdx.x) >> 5);
    if (w >= g_nneed) return;
    int d = g_needlist[w];
    int lane = threadIdx.x & 31;
    int beg = g_off[d], end = g_cur[d];
    float dd = g_dinv[d];
    float ax = 0.f, ay = 0.f;
    int i = beg;
    for (; i + 8 <= end; i += 8) {
        int s0 = __ldg(&g_csr[i]),     s1 = __ldg(&g_csr[i + 1]);
        int s2 = __ldg(&g_csr[i + 2]), s3 = __ldg(&g_csr[i + 3]);
        int s4 = __ldg(&g_csr[i + 4]), s5 = __ldg(&g_csr[i + 5]);
        int s6 = __ldg(&g_csr[i + 6]), s7 = __ldg(&g_csr[i + 7]);
        float w0 = __ldg(&g_dinv[s0]), w1 = __ldg(&g_dinv[s1]);
        float w2 = __ldg(&g_dinv[s2]), w3 = __ldg(&g_dinv[s3]);
        float w4 = __ldg(&g_dinv[s4]), w5 = __ldg(&g_dinv[s5]);
        float w6 = __ldg(&g_dinv[s6]), w7 = __ldg(&g_dinv[s7]);
        float2 x0 = __ldg(((const float2*)(X + s0 * NINP)) + lane);
        float2 x1 = __ldg(((const float2*)(X + s1 * NINP)) + lane);
        float2 x2 = __ldg(((const float2*)(X + s2 * NINP)) + lane);
        float2 x3 = __ldg(((const float2*)(X + s3 * NINP)) + lane);
        float2 x4 = __ldg(((const float2*)(X + s4 * NINP)) + lane);
        float2 x5 = __ldg(((const float2*)(X + s5 * NINP)) + lane);
        float2 x6 = __ldg(((const float2*)(X + s6 * NINP)) + lane);
        float2 x7 = __ldg(((const float2*)(X + s7 * NINP)) + lane);
        ax += w0 * x0.x + w1 * x1.x + w2 * x2.x + w3 * x3.x
            + w4 * x4.x + w5 * x5.x + w6 * x6.x + w7 * x7.x;
        ay += w0 * x0.y + w1 * x1.y + w2 * x2.y + w3 * x3.y
            + w4 * x4.y + w5 * x5.y + w6 * x6.y + w7 * x7.y;
    }
    for (; i + 4 <= end; i += 4) {
        int s0 = __ldg(&g_csr[i]),     s1 = __ldg(&g_csr[i + 1]);
        int s2 = __ldg(&g_csr[i + 2]), s3 = __ldg(&g_csr[i + 3]);
        float w0 = __ldg(&g_dinv[s0]), w1 = __ldg(&g_dinv[s1]);
        float w2 = __ldg(&g_dinv[s2]), w3 = __ldg(&g_dinv[s3]);
        float2 x0 = __ldg(((const float2*)(X + s0 * NINP)) + lane);
        float2 x1 = __ldg(((const float2*)(X + s1 * NINP)) + lane);
        float2 x2 = __ldg(((const float2*)(X + s2 * NINP)) + lane);
        float2 x3 = __ldg(((const float2*)(X + s3 * NINP)) + lane);
        ax += w0 * x0.x + w1 * x1.x + w2 * x2.x + w3 * x3.x;
        ay += w0 * x0.y + w1 * x1.y + w2 * x2.y + w3 * x3.y;
    }
    for (; i < end; i++) {
        int s = __ldg(&g_csr[i]);
        float ww = __ldg(&g_dinv[s]);
        float2 x = __ldg(((const float2*)(X + s * NINP)) + lane);
        ax += ww * x.x; ay += ww * x.y;
    }
    ax *= dd; ay *= dd;                              // hoist dd out of the sum
    float2 xs = __ldg(((const float2*)(X + d * NINP)) + lane);
    float sw = dd * dd;
    ax += sw * xs.x; ay += sw * xs.y;
    ((float2*)(g_y + d * NINP))[lane] = make_float2(ax, ay);
}

// K8: gather pass 2 — warp per unique token node
__global__ void k_gather2() {
    int w = (int)(((long long)blockIdx.x * blockDim.x + threadIdx.x) >> 5);
    if (w >= g_ntok) return;
    int d = g_toklist[w];
    int lane = threadIdx.x & 31;
    int beg = g_off[d], end = g_cur[d];
    float dd = g_dinv[d];
    float ax = 0.f, ay = 0.f, cw = 0.f;
    int i = beg;
    for (; i + 4 <= end; i += 4) {
        int s0 = __ldg(&g_csr[i]),     s1 = __ldg(&g_csr[i + 1]);
        int s2 = __ldg(&g_csr[i + 2]), s3 = __ldg(&g_csr[i + 3]);
        float w0 = __ldg(&g_dinv[s0]), w1 = __ldg(&g_dinv[s1]);
        float w2 = __ldg(&g_dinv[s2]), w3 = __ldg(&g_dinv[s3]);
        float2 x0 = ((const float2*)(g_y + s0 * NINP))[lane];
        float2 x1 = ((const float2*)(g_y + s1 * NINP))[lane];
        float2 x2 = ((const float2*)(g_y + s2 * NINP))[lane];
        float2 x3 = ((const float2*)(g_y + s3 * NINP))[lane];
        ax += w0 * x0.x + w1 * x1.x + w2 * x2.x + w3 * x3.x;
        ay += w0 * x0.y + w1 * x1.y + w2 * x2.y + w3 * x3.y;
        cw += w0 + w1 + w2 + w3;
    }
    for (; i < end; i++) {
        int s = __ldg(&g_csr[i]);
        float ww = __ldg(&g_dinv[s]);
        float2 x = ((const float2*)(g_y + s * NINP))[lane];
        ax += ww * x.x; ay += ww * x.y; cw += ww;
    }
    ax *= dd; ay *= dd; cw *= dd;
    float sw = dd * dd;
    float2 ys = ((const float2*)(g_y + d * NINP))[lane];
    ax += sw * ys.x; ay += sw * ys.y; cw += sw;
    ((float2*)(g_z + d * NINP))[lane] = make_float2(ax, ay);
    if (lane == 0) g_c[d] = cw;
}

// K9: W12 = W1@W2, bW = b1@W2
__global__ void k_w12(const float* __restrict__ W1, const float* __restrict__ b1,
                      const float* __restrict__ W2) {
    int j = threadIdx.x;
    int b = blockIdx.x;
    float acc = 0.f;
    if (b < NINP) {
        #pragma unroll 8
        for (int k = 0; k < 2 * NINP; k++) acc += W1[b * 2 * NINP + k] * W2[k * NINP + j];
        g_W12[b * NINP + j] = acc;
    } else {
        #pragma unroll 8
        for (int k = 0; k < 2 * NINP; k++) acc += b1[k] * W2[k * NINP + j];
        g_bW[j] = acc;
    }
}

// K10: out[n,j] = z[tok].W12[:,j] + c[tok]*bW[j] + b2[j]
__global__ void k_out(const void* __restrict__ inp, const float* __restrict__ b2,
                      float* __restrict__ out) {
    __shared__ float sW[NINP * NINP];
    __shared__ float sz[4][NINP];
    __shared__ float sc[4];
    int tid = threadIdx.x;
    int g = tid >> 6;
    int j = tid & 63;
    int n = blockIdx.x * 4 + g;
    int is64 = g_is64;

    for (int i = tid; i < NINP * NINP; i += 256) sW[i] = g_W12[i];
    int tok = (int)ld_idx(inp, n, is64);
    sz[g][j] = g_z[tok * NINP + j];
    if (j == 0) sc[g] = g_c[tok];
    __syncthreads();

    float acc = 0.f;
    #pragma unroll
    for (int i = 0; i < NINP; i++) acc += sz[g][i] * sW[i * NINP + j];
    out[n * NINP + j] = acc + sc[g] * g_bW[j] + b2[j];
}

// ---------------------------------------------------------------------------
extern "C" void kernel_launch(void* const* d_in, const int* in_sizes, int n_in,
                              void* d_out, int out_size) {
    const float* emb = (const float*)d_in[0];
    const float* W1  = (const float*)d_in[1];
    const float* b1  = (const float*)d_in[2];
    const float* W2  = (const float*)d_in[3];
    const float* b2  = (const float*)d_in[4];
    const void*  inp = d_in[5];
    const void*  eidx = d_in[7];
    float* out = (float*)d_out;

    const int TB = 256;
    k_zero<<<(NTOKEN + TB - 1) / TB, TB>>>(eidx);
    k_tokbm<<<(NBL + TB - 1) / TB, TB>>>(inp);
    k_deg<<<(NEDGE + TB - 1) / TB, TB>>>(eidx);
    k_bsum<<<NB_SCAN, 256>>>();
    k_btop<<<1, 1024>>>();
    k_offs<<<NB_SCAN, 256>>>();
    k_fill<<<(NEDGE / 2 + TB - 1) / TB, TB>>>();
    k_gather1<<<(NTOKEN * 32 + TB - 1) / TB, TB>>>(emb);
    k_gather2<<<(NBL * 32 + TB - 1) / TB, TB>>>();
    k_w12<<<NINP + 1, NINP>>>(W1, b1, W2);
    k_out<<<NBL / 4, TB>>>(inp, b2, out);
}